// round 1
// baseline (speedup 1.0000x reference)
#include <cuda_runtime.h>
#include <cstddef>

// Problem constants
#define BB 8
#define CC 2
#define DIN 96
#define HIN 64
#define WIN 64
#define FF 8
#define DD 3
#define HH 60
#define WW 64
#define DOUT 94        // 96 - 3 + 1
#define MARGIN 4       // 64 - 60
#define TT 4           // t-group size
#define NTG 24         // ceil(94/4)
#define LEAKY 0.2f

// Precomputed bias box-sum: Bc[f][y][x] = sum over c,dd and valid 3x3 window of bias
__device__ float g_Bc[FF * HH * WW];

__global__ void bconv_kernel(const float* __restrict__ bias) {
    int idx = blockIdx.x * blockDim.x + threadIdx.x;
    if (idx >= FF * HH * WW) return;
    int x = idx & 63;
    int y = (idx >> 6) % HH;
    int f = idx / (HH * WW);
    float s = 0.f;
    for (int c = 0; c < CC; c++) {
        for (int dd = 0; dd < DD; dd++) {
            const float* bp = bias + (((f * CC + c) * DD + dd) * HH) * WW;
            for (int dy = -1; dy <= 1; dy++) {
                int yy = y + dy;
                if (yy < 0 || yy >= HH) continue;
                for (int dx = -1; dx <= 1; dx++) {
                    int xx = x + dx;
                    if (xx < 0 || xx >= WW) continue;
                    s += bp[yy * WW + xx];
                }
            }
        }
    }
    g_Bc[idx] = s;
}

// Main fused kernel.
// Grid: x = tg*2 + half  (48), y = b (8).  Block: 512 threads.
// Thread (ty = tid/16 in [0,32), xi = tid%16) owns T-row ys = y0-1+ty, x-cols [4*xi, 4*xi+4).
// Tp[t][ty][col]: padded T buffer. col 4+x holds T at x; cols 0..3 and 68..71 are zero pad
// (col 3 = x=-1, col 68 = x=64). Row ty holds T row y0-1+ty; out-of-range rows stay zero.
__global__ __launch_bounds__(512, 1)
void linconv_main(const float* __restrict__ in,
                  const float* __restrict__ wgt,
                  float* __restrict__ out) {
    __shared__ float Tp[TT][32][72];

    const int b     = blockIdx.y;
    const int tg    = blockIdx.x >> 1;
    const int half  = blockIdx.x & 1;
    const int tbase = tg * TT;
    const int tcnt  = min(TT, DOUT - tbase);
    const int y0    = half * 30;
    const int tid   = threadIdx.x;
    const int ty    = tid >> 4;
    const int xi    = tid & 15;
    const int x     = xi * 4;
    const int ys    = y0 - 1 + ty;                    // T row this thread builds
    const bool vrow = (ys >= 0 && ys < HH);

    // zero entire padded T buffers (pads stay zero forever)
    {
        float* p = &Tp[0][0][0];
        for (int i = tid; i < TT * 32 * 72; i += 512) p[i] = 0.f;
    }

    // S[c][zi] = 5-row vertical sum of input at (b, c, tbase+zi, ys.., x..x+3), in registers
    float4 S[CC][TT + 2];
    #pragma unroll
    for (int c = 0; c < CC; c++) {
        #pragma unroll
        for (int zi = 0; zi < TT + 2; zi++) {
            float4 s = make_float4(0.f, 0.f, 0.f, 0.f);
            if (vrow && zi < tcnt + 2) {
                const float* p = in + (((size_t)(b * CC + c) * DIN + (tbase + zi)) * HIN + ys) * WIN + x;
                #pragma unroll
                for (int j = 0; j < 5; j++) {
                    float4 v = *(const float4*)(p + j * WIN);
                    s.x += v.x; s.y += v.y; s.z += v.z; s.w += v.w;
                }
            }
            S[c][zi] = s;
        }
    }
    __syncthreads();

    for (int f = 0; f < FF; f++) {
        // ---- build phase: T for all t in group, this f ----
        if (vrow) {
            float4 Wr[CC][DD];
            #pragma unroll
            for (int c = 0; c < CC; c++)
                #pragma unroll
                for (int dd = 0; dd < DD; dd++)
                    Wr[c][dd] = *(const float4*)(wgt + (((f * CC + c) * DD + dd) * HH + ys) * WW + x);

            #pragma unroll
            for (int t = 0; t < TT; t++) {
                if (t < tcnt) {
                    float4 a = make_float4(0.f, 0.f, 0.f, 0.f);
                    #pragma unroll
                    for (int c = 0; c < CC; c++) {
                        #pragma unroll
                        for (int dd = 0; dd < DD; dd++) {
                            float4 s = S[c][t + dd];
                            float4 w = Wr[c][dd];
                            a.x = fmaf(s.x, w.x, a.x);
                            a.y = fmaf(s.y, w.y, a.y);
                            a.z = fmaf(s.z, w.z, a.z);
                            a.w = fmaf(s.w, w.w, a.w);
                        }
                    }
                    *(float4*)&Tp[t][ty][4 + x] = a;
                }
            }
        }
        __syncthreads();

        // ---- consume phase: 3x3 box sum + bias + leaky_relu + store ----
        const int nwork = tcnt * 480;                 // 30 rows * 16 x-groups per t
        for (int u = tid; u < nwork; u += 512) {
            int t  = u / 480;
            int r  = u - t * 480;
            int yl = r >> 4;                          // 0..29
            int xc = (r & 15) * 4;
            const float* base = &Tp[t][yl][4 + xc];   // T row yo-1 at this col
            float4 r0 = *(const float4*)(base);
            float4 r1 = *(const float4*)(base + 72);
            float4 r2 = *(const float4*)(base + 144);
            float vx = r0.x + r1.x + r2.x;
            float vy = r0.y + r1.y + r2.y;
            float vz = r0.z + r1.z + r2.z;
            float vw = r0.w + r1.w + r2.w;
            float lv = base[-1] + base[71] + base[143];   // column x-1
            float rv = base[4]  + base[76] + base[148];   // column x+4
            int yo = y0 + yl;
            float4 bc = *(const float4*)(g_Bc + (f * HH + yo) * WW + xc);
            float o0 = 0.25f * (lv + vx + vy + bc.x);
            float o1 = 0.25f * (vx + vy + vz + bc.y);
            float o2 = 0.25f * (vy + vz + vw + bc.z);
            float o3 = 0.25f * (vz + vw + rv + bc.w);
            o0 = (o0 > 0.f) ? o0 : LEAKY * o0;
            o1 = (o1 > 0.f) ? o1 : LEAKY * o1;
            o2 = (o2 > 0.f) ? o2 : LEAKY * o2;
            o3 = (o3 > 0.f) ? o3 : LEAKY * o3;
            float* op = out + ((((size_t)b * FF + f) * DOUT + (tbase + t)) * HH + yo) * WW + xc;
            *(float4*)op = make_float4(o0, o1, o2, o3);
        }
        __syncthreads();
    }
}

extern "C" void kernel_launch(void* const* d_in, const int* in_sizes, int n_in,
                              void* d_out, int out_size) {
    const float* in   = (const float*)d_in[0];
    const float* wgt  = (const float*)d_in[1];
    const float* bias = (const float*)d_in[2];
    float* out        = (float*)d_out;

    bconv_kernel<<<(FF * HH * WW + 255) / 256, 256>>>(bias);

    dim3 grid(NTG * 2, BB);
    linconv_main<<<grid, 512>>>(in, wgt, out);
}

// round 2
// speedup vs baseline: 1.0388x; 1.0388x over previous
#include <cuda_runtime.h>
#include <cstddef>

// Problem constants
#define BB 8
#define CC 2
#define DIN 96
#define HIN 64
#define WIN 64
#define FF 8
#define DD 3
#define HH 60
#define WW 64
#define DOUT 94        // 96 - 3 + 1
#define TT 4           // t-group size
#define NTG 24         // ceil(94/4)
#define LEAKY 0.2f

#define SMEM_FLOATS (2 * TT * 32 * 72)
#define TP(buf,t,ty,col) smem[((((buf)*TT+(t))*32+(ty))*72)+(col)]

// Precomputed bias box-sum: Bc[f][y][x] = sum over c,dd and valid 3x3 window of bias
__device__ float g_Bc[FF * HH * WW];

__global__ void bconv_kernel(const float* __restrict__ bias) {
    int idx = blockIdx.x * blockDim.x + threadIdx.x;
    if (idx >= FF * HH * WW) return;
    int x = idx & 63;
    int y = (idx >> 6) % HH;
    int f = idx / (HH * WW);
    float s = 0.f;
    for (int c = 0; c < CC; c++) {
        for (int dd = 0; dd < DD; dd++) {
            const float* bp = bias + (((f * CC + c) * DD + dd) * HH) * WW;
            for (int dy = -1; dy <= 1; dy++) {
                int yy = y + dy;
                if (yy < 0 || yy >= HH) continue;
                for (int dx = -1; dx <= 1; dx++) {
                    int xx = x + dx;
                    if (xx < 0 || xx >= WW) continue;
                    s += bp[yy * WW + xx];
                }
            }
        }
    }
    g_Bc[idx] = s;
}

// Build T for feature f into buffer `buf`.
__device__ __forceinline__ void build_T(float* smem, int buf, int f,
                                        const float4 (&S)[CC][TT + 2],
                                        const float* __restrict__ wgt,
                                        int ys, int x, int ty, int tcnt, bool vrow) {
    if (!vrow) return;
    float4 Wr[CC][DD];
    #pragma unroll
    for (int c = 0; c < CC; c++)
        #pragma unroll
        for (int dd = 0; dd < DD; dd++)
            Wr[c][dd] = *(const float4*)(wgt + (((f * CC + c) * DD + dd) * HH + ys) * WW + x);

    #pragma unroll
    for (int t = 0; t < TT; t++) {
        if (t < tcnt) {
            float4 a = make_float4(0.f, 0.f, 0.f, 0.f);
            #pragma unroll
            for (int c = 0; c < CC; c++) {
                #pragma unroll
                for (int dd = 0; dd < DD; dd++) {
                    float4 s = S[c][t + dd];
                    float4 w = Wr[c][dd];
                    a.x = fmaf(s.x, w.x, a.x);
                    a.y = fmaf(s.y, w.y, a.y);
                    a.z = fmaf(s.z, w.z, a.z);
                    a.w = fmaf(s.w, w.w, a.w);
                }
            }
            *(float4*)&TP(buf, t, ty, 4 + x) = a;
        }
    }
}

// Main fused kernel, software-pipelined over f with double-buffered T.
// Grid: x = tg*2 + half  (48), y = b (8).  Block: 512 threads.
// Thread (ty = tid/16, xi = tid%16) owns T-row ys = y0-1+ty, x-cols [4*xi, 4*xi+4).
// Tp[buf][t][ty][col]: padded T buffer; cols 0..3 and 68..71 + out-of-range rows
// stay zero forever (zeroed once at start).
__global__ __launch_bounds__(512, 1)
void linconv_main(const float* __restrict__ in,
                  const float* __restrict__ wgt,
                  float* __restrict__ out) {
    extern __shared__ float smem[];

    const int b     = blockIdx.y;
    const int tg    = blockIdx.x >> 1;
    const int half  = blockIdx.x & 1;
    const int tbase = tg * TT;
    const int tcnt  = min(TT, DOUT - tbase);
    const int y0    = half * 30;
    const int tid   = threadIdx.x;
    const int ty    = tid >> 4;
    const int xi    = tid & 15;
    const int x     = xi * 4;
    const int ys    = y0 - 1 + ty;                    // T row this thread builds
    const bool vrow = (ys >= 0 && ys < HH);

    // zero both padded T buffers (pads + dead rows stay zero forever)
    for (int i = tid; i < SMEM_FLOATS; i += 512) smem[i] = 0.f;

    // S[c][zi] = 5-row vertical sum of input at (b, c, tbase+zi, ys.., x..x+3), in registers
    float4 S[CC][TT + 2];
    #pragma unroll
    for (int c = 0; c < CC; c++) {
        #pragma unroll
        for (int zi = 0; zi < TT + 2; zi++) {
            float4 s = make_float4(0.f, 0.f, 0.f, 0.f);
            if (vrow && zi < tcnt + 2) {
                const float* p = in + (((size_t)(b * CC + c) * DIN + (tbase + zi)) * HIN + ys) * WIN + x;
                #pragma unroll
                for (int j = 0; j < 5; j++) {
                    float4 v = *(const float4*)(p + j * WIN);
                    s.x += v.x; s.y += v.y; s.z += v.z; s.w += v.w;
                }
            }
            S[c][zi] = s;
        }
    }
    __syncthreads();          // zeroing complete (also orders before first build)

    // prologue: build f=0 into buffer 0
    build_T(smem, 0, 0, S, wgt, ys, x, ty, tcnt, vrow);
    __syncthreads();

    const int nwork = tcnt * 480;                     // 30 rows * 16 x-groups per t

    #pragma unroll 1
    for (int f = 0; f < FF; f++) {
        const int cur = f & 1;

        // ---- build phase for f+1 into the other buffer (overlaps with consume) ----
        if (f + 1 < FF)
            build_T(smem, cur ^ 1, f + 1, S, wgt, ys, x, ty, tcnt, vrow);

        // ---- consume phase: 3x3 box sum + bias + leaky_relu + store (reads buf cur) ----
        for (int u = tid; u < nwork; u += 512) {
            int t  = u / 480;
            int r  = u - t * 480;
            int yl = r >> 4;                          // 0..29
            int xc = (r & 15) * 4;
            const float* base = &TP(cur, t, yl, 4 + xc);   // T row yo-1 at this col
            float4 r0 = *(const float4*)(base);
            float4 r1 = *(const float4*)(base + 72);
            float4 r2 = *(const float4*)(base + 144);
            float vx = r0.x + r1.x + r2.x;
            float vy = r0.y + r1.y + r2.y;
            float vz = r0.z + r1.z + r2.z;
            float vw = r0.w + r1.w + r2.w;
            float lv = base[-1] + base[71] + base[143];   // column x-1
            float rv = base[4]  + base[76] + base[148];   // column x+4
            int yo = y0 + yl;
            float4 bc = *(const float4*)(g_Bc + (f * HH + yo) * WW + xc);
            float o0 = 0.25f * (lv + vx + vy + bc.x);
            float o1 = 0.25f * (vx + vy + vz + bc.y);
            float o2 = 0.25f * (vy + vz + vw + bc.z);
            float o3 = 0.25f * (vz + vw + rv + bc.w);
            o0 = (o0 > 0.f) ? o0 : LEAKY * o0;
            o1 = (o1 > 0.f) ? o1 : LEAKY * o1;
            o2 = (o2 > 0.f) ? o2 : LEAKY * o2;
            o3 = (o3 > 0.f) ? o3 : LEAKY * o3;
            float* op = out + ((((size_t)b * FF + f) * DOUT + (tbase + t)) * HH + yo) * WW + xc;
            *(float4*)op = make_float4(o0, o1, o2, o3);
        }
        __syncthreads();
    }
}

extern "C" void kernel_launch(void* const* d_in, const int* in_sizes, int n_in,
                              void* d_out, int out_size) {
    const float* in   = (const float*)d_in[0];
    const float* wgt  = (const float*)d_in[1];
    const float* bias = (const float*)d_in[2];
    float* out        = (float*)d_out;

    static bool attr_set = false;
    if (!attr_set) {
        cudaFuncSetAttribute(linconv_main,
                             cudaFuncAttributeMaxDynamicSharedMemorySize,
                             SMEM_FLOATS * sizeof(float));
        attr_set = true;
    }

    bconv_kernel<<<(FF * HH * WW + 255) / 256, 256>>>(bias);

    dim3 grid(NTG * 2, BB);
    linconv_main<<<grid, 512, SMEM_FLOATS * sizeof(float)>>>(in, wgt, out);
}